// round 6
// baseline (speedup 1.0000x reference)
#include <cuda_runtime.h>
#include <math.h>

#define Nn     2048
#define Ee     4096
#define NODE_K 1024
#define EDGE_K 2048
#define CAP    128      // adjacency list capacity (realistic max ~2*max_degree ≈ 35)

// ---------------- scratch (static device memory; no allocs) ----------------
__device__ float g_f[4761600];
__device__ int   g_i[530432];

// float offsets into g_f
#define OFF_NS    0
#define OFF_ES    2048
#define OFF_EMASK 6144
#define OFF_ACAT  10240      // [E][256]
#define OFF_WCAT  1058816    // [256][128]
#define OFF_H     1091584    // [E][128]
#define OFF_Q     1615872
#define OFF_K     2140160
#define OFF_V     2664448
#define OFF_ATT   3188736
#define OFF_T1    3713024
#define OFF_T2    4237312
// int offsets into g_i
#define IOFF_NMASK  0        // [N]
#define IOFF_ADJCNT 2048     // [E]
#define IOFF_ADJ    6144     // [E][CAP]

// ---------------- router scores: one warp per row ----------------
__global__ void router_scores_kernel(const float* __restrict__ nf,
                                     const float* __restrict__ ef,
                                     const float* __restrict__ wrn,
                                     const float* __restrict__ wre)
{
    int w    = (blockIdx.x * blockDim.x + threadIdx.x) >> 5;
    int lane = threadIdx.x & 31;
    if (w >= Nn + Ee) return;
    const float* row; const float* wt; float* outp; int idx;
    if (w < Nn) { idx = w;      row = nf + (size_t)idx * 128; wt = wrn; outp = g_f + OFF_NS; }
    else        { idx = w - Nn; row = ef + (size_t)idx * 128; wt = wre; outp = g_f + OFF_ES; }
    float s = 0.f;
    #pragma unroll
    for (int i = lane; i < 128; i += 32) s += row[i] * wt[i];
    #pragma unroll
    for (int o = 16; o; o >>= 1) s += __shfl_xor_sync(0xffffffffu, s, o);
    if (lane == 0) outp[idx] = s;
}

// ---------------- top-k node mask (O(N^2) rank count) ----------------
__global__ void topk_node_kernel()
{
    __shared__ float s[Nn];
    const float* ns = g_f + OFF_NS;
    for (int i = threadIdx.x; i < Nn; i += blockDim.x) s[i] = ns[i];
    __syncthreads();
    int i = blockIdx.x * blockDim.x + threadIdx.x;
    float v = s[i];
    int cnt = 0;
    for (int j = 0; j < Nn; j++) {
        float u = s[j];
        cnt += (u > v) || (u == v && j < i);   // top_k tie-break: value desc, then index asc
    }
    g_i[IOFF_NMASK + i] = (cnt < NODE_K) ? 1 : 0;
}

// ---------------- top-k edge mask AND endpoint node masks ----------------
__global__ void topk_edge_kernel(const int* __restrict__ ei)
{
    __shared__ float s[Ee];
    const float* es = g_f + OFF_ES;
    for (int i = threadIdx.x; i < Ee; i += blockDim.x) s[i] = es[i];
    __syncthreads();
    int i = blockIdx.x * blockDim.x + threadIdx.x;
    float v = s[i];
    int cnt = 0;
    for (int j = 0; j < Ee; j++) {
        float u = s[j];
        cnt += (u > v) || (u == v && j < i);
    }
    int in_top = (cnt < EDGE_K);
    int sn = ei[i], dn = ei[Ee + i];
    const int* nmask = g_i + IOFF_NMASK;
    g_f[OFF_EMASK + i] = (in_top && nmask[sn] && nmask[dn]) ? 1.0f : 0.0f;
}

// ---------------- A_cat = [ef * emask | nf[src]+nf[dst]]  (E x 256) ----------------
__global__ void prep_acat_kernel(const float* __restrict__ ef,
                                 const float* __restrict__ nf,
                                 const int* __restrict__ ei)
{
    int idx = blockIdx.x * blockDim.x + threadIdx.x;   // E*256 threads
    int e = idx >> 8, c = idx & 255;
    float v;
    if (c < 128) {
        v = ef[(size_t)e * 128 + c] * g_f[OFF_EMASK + e];
    } else {
        int cc = c - 128;
        int sn = ei[e], dn = ei[Ee + e];
        v = nf[(size_t)sn * 128 + cc] + nf[(size_t)dn * 128 + cc];
    }
    g_f[OFF_ACAT + (size_t)e * 256 + c] = v;
}

// ---------------- W_cat = [w_e ; w_n]  (256 x 128) ----------------
__global__ void copy_wcat_kernel(const float* __restrict__ we,
                                 const float* __restrict__ wn)
{
    int i = blockIdx.x * blockDim.x + threadIdx.x;   // 16384 threads
    g_f[OFF_WCAT + i]         = we[i];
    g_f[OFF_WCAT + 16384 + i] = wn[i];
}

// ---------------- generic GEMM: C[M,128] = act(A[M,K] @ W[K,128] + bias) ----------------
// A is scratch (offset a_off). W is external (Wext) unless null -> g_f + w_off.
// BM=32 rows/block, 128 threads, each thread 4 rows x 8 cols. act: 0=none, 1=gelu(tanh)
__device__ __forceinline__ float gelu_tanh(float x) {
    const float k0 = 0.7978845608028654f;   // sqrt(2/pi)
    float x3 = x * x * x;
    return 0.5f * x * (1.0f + tanhf(k0 * (x + 0.044715f * x3)));
}

__global__ __launch_bounds__(128) void gemm128_kernel(
    int a_off, int K,
    const float* __restrict__ Wext, int w_off,
    const float* __restrict__ bias,
    int act,
    int c_off)
{
    const float* A = g_f + a_off;
    const float* W = Wext ? Wext : (const float*)(g_f + w_off);
    float* C = g_f + c_off;

    __shared__ float As[32][33];    // [k][m], padded
    __shared__ float Ws[32][128];   // [k][n]
    int tid = threadIdx.x;
    int ty = tid >> 4;              // 0..7 -> rows ty*4 .. ty*4+3
    int tx = tid & 15;              // cols tx*4..+3 and 64+tx*4..+3
    int row0 = blockIdx.x * 32;

    float acc[4][8];
    #pragma unroll
    for (int i = 0; i < 4; i++)
        #pragma unroll
        for (int j = 0; j < 8; j++) acc[i][j] = 0.f;

    for (int k0 = 0; k0 < K; k0 += 32) {
        #pragma unroll
        for (int i = tid; i < 32 * 32; i += 128) {
            int r = i >> 5, c = i & 31;
            As[c][r] = A[(size_t)(row0 + r) * K + (k0 + c)];
        }
        #pragma unroll
        for (int i = tid; i < 32 * 32; i += 128) {
            int r = i >> 5, c = i & 31;
            ((float4*)&Ws[r][0])[c] = ((const float4*)(W + (size_t)(k0 + r) * 128))[c];
        }
        __syncthreads();
        #pragma unroll
        for (int kk = 0; kk < 32; kk++) {
            float a0 = As[kk][ty * 4 + 0];
            float a1 = As[kk][ty * 4 + 1];
            float a2 = As[kk][ty * 4 + 2];
            float a3 = As[kk][ty * 4 + 3];
            float4 w0 = ((float4*)&Ws[kk][0])[tx];
            float4 w1 = ((float4*)&Ws[kk][0])[16 + tx];
            acc[0][0] += a0 * w0.x; acc[0][1] += a0 * w0.y; acc[0][2] += a0 * w0.z; acc[0][3] += a0 * w0.w;
            acc[0][4] += a0 * w1.x; acc[0][5] += a0 * w1.y; acc[0][6] += a0 * w1.z; acc[0][7] += a0 * w1.w;
            acc[1][0] += a1 * w0.x; acc[1][1] += a1 * w0.y; acc[1][2] += a1 * w0.z; acc[1][3] += a1 * w0.w;
            acc[1][4] += a1 * w1.x; acc[1][5] += a1 * w1.y; acc[1][6] += a1 * w1.z; acc[1][7] += a1 * w1.w;
            acc[2][0] += a2 * w0.x; acc[2][1] += a2 * w0.y; acc[2][2] += a2 * w0.z; acc[2][3] += a2 * w0.w;
            acc[2][4] += a2 * w1.x; acc[2][5] += a2 * w1.y; acc[2][6] += a2 * w1.z; acc[2][7] += a2 * w1.w;
            acc[3][0] += a3 * w0.x; acc[3][1] += a3 * w0.y; acc[3][2] += a3 * w0.z; acc[3][3] += a3 * w0.w;
            acc[3][4] += a3 * w1.x; acc[3][5] += a3 * w1.y; acc[3][6] += a3 * w1.z; acc[3][7] += a3 * w1.w;
        }
        __syncthreads();
    }

    #pragma unroll
    for (int i = 0; i < 4; i++) {
        int r = row0 + ty * 4 + i;
        #pragma unroll
        for (int g = 0; g < 2; g++) {
            #pragma unroll
            for (int j = 0; j < 4; j++) {
                int c = g * 64 + tx * 4 + j;
                float v = acc[i][g * 4 + j];
                if (bias) v += bias[c];
                if (act == 1) v = gelu_tanh(v);
                C[(size_t)r * 128 + c] = v;
            }
        }
    }
}

// ---------------- adjacency lists: one warp per query edge, ballot compaction ----------------
__global__ void build_adj_kernel(const int* __restrict__ ei)
{
    int e    = blockIdx.x * (blockDim.x >> 5) + (threadIdx.x >> 5);
    int lane = threadIdx.x & 31;
    int qs = ei[e], qd = ei[Ee + e];
    int* adj = g_i + IOFF_ADJ + (size_t)e * CAP;
    int cnt = 0;
    for (int j0 = 0; j0 < Ee; j0 += 32) {
        int f  = j0 + lane;
        int fs = ei[f], fd = ei[Ee + f];
        bool a = (qs == fs) | (qs == fd) | (qd == fs) | (qd == fd);
        unsigned b = __ballot_sync(0xffffffffu, a);
        if (a) {
            int pos = cnt + __popc(b & ((1u << lane) - 1u));
            if (pos < CAP) adj[pos] = f;
        }
        cnt += __popc(b);
    }
    if (lane == 0) g_i[IOFF_ADJCNT + e] = (cnt < CAP) ? cnt : CAP;
}

// ---------------- sparse attention: one thread per (edge, head), online softmax ----------------
__global__ __launch_bounds__(128) void attention_kernel()
{
    int t = blockIdx.x * blockDim.x + threadIdx.x;   // E*H threads
    int e = t >> 2;
    int h = t & 3;

    const float* q = g_f + OFF_Q;
    const float* k = g_f + OFF_K;
    const float* v = g_f + OFF_V;

    float qr[32];
    const float4* qp = (const float4*)(q + (size_t)e * 128 + h * 32);
    #pragma unroll
    for (int d = 0; d < 8; d++) {
        float4 qq = qp[d];
        qr[d * 4 + 0] = qq.x; qr[d * 4 + 1] = qq.y; qr[d * 4 + 2] = qq.z; qr[d * 4 + 3] = qq.w;
    }

    float m = -INFINITY, l = 0.f;
    float o[32];
    #pragma unroll
    for (int d = 0; d < 32; d++) o[d] = 0.f;

    const float scale = 0.17677669529663687f;   // 1/sqrt(32)
    int cnt = g_i[IOFF_ADJCNT + e];
    const int* myadj = g_i + IOFF_ADJ + (size_t)e * CAP;

    for (int i = 0; i < cnt; i++) {
        int f = myadj[i];
        const float4* kp = (const float4*)(k + (size_t)f * 128 + h * 32);
        float s = 0.f;
        #pragma unroll
        for (int d = 0; d < 8; d++) {
            float4 kk = kp[d];
            s += qr[d * 4 + 0] * kk.x + qr[d * 4 + 1] * kk.y
               + qr[d * 4 + 2] * kk.z + qr[d * 4 + 3] * kk.w;
        }
        s *= scale;
        if (s > m) {
            float c = expf(m - s);   // first iter: expf(-inf)=0
            l *= c;
            #pragma unroll
            for (int d = 0; d < 32; d++) o[d] *= c;
            m = s;
        }
        float p = expf(s - m);
        l += p;
        const float4* vp = (const float4*)(v + (size_t)f * 128 + h * 32);
        #pragma unroll
        for (int d = 0; d < 8; d++) {
            float4 vv = vp[d];
            o[d * 4 + 0] += p * vv.x; o[d * 4 + 1] += p * vv.y;
            o[d * 4 + 2] += p * vv.z; o[d * 4 + 3] += p * vv.w;
        }
    }

    float inv = 1.0f / l;
    float* op = g_f + OFF_ATT + (size_t)e * 128 + h * 32;
    #pragma unroll
    for (int d = 0; d < 32; d++) op[d] = o[d] * inv;
}

// ---------------- final classifier layer: logits[E,16] ----------------
__global__ void final_fc_kernel(const float* __restrict__ w2,
                                const float* __restrict__ b2,
                                float* __restrict__ out)
{
    int t = blockIdx.x * blockDim.x + threadIdx.x;   // E*16 threads
    int e = t >> 4, c = t & 15;
    float acc = b2[c];
    const float* xr = g_f + OFF_T2 + (size_t)e * 128;
    #pragma unroll 4
    for (int kk = 0; kk < 128; kk++) acc += xr[kk] * w2[kk * 16 + c];
    out[t] = acc;
}

// ---------------- launcher: pure kernel launches, graph-capture-safe ----------------
extern "C" void kernel_launch(void* const* d_in, const int* in_sizes, int n_in,
                              void* d_out, int out_size)
{
    (void)in_sizes; (void)n_in; (void)out_size;
    const float* nf   = (const float*)d_in[0];
    const float* ef   = (const float*)d_in[1];
    const int*   ei   = (const int*)  d_in[2];
    const float* wrn  = (const float*)d_in[3];
    const float* wre  = (const float*)d_in[4];
    const float* w_e  = (const float*)d_in[5];
    const float* w_n  = (const float*)d_in[6];
    const float* w_q  = (const float*)d_in[7];
    const float* w_k  = (const float*)d_in[8];
    const float* w_v  = (const float*)d_in[9];
    const float* w_o  = (const float*)d_in[10];
    const float* w1   = (const float*)d_in[11];
    const float* b1   = (const float*)d_in[12];
    const float* w2   = (const float*)d_in[13];
    const float* b2   = (const float*)d_in[14];
    float* out = (float*)d_out;

    // 1) router scores (N+E warps)
    router_scores_kernel<<<(Nn + Ee) * 32 / 256, 256>>>(nf, ef, wrn, wre);
    // 2) top-k masks
    topk_node_kernel<<<Nn / 256, 256>>>();
    topk_edge_kernel<<<Ee / 256, 256>>>(ei);
    // 3) concatenated input + weight
    prep_acat_kernel<<<(Ee * 256) / 256, 256>>>(ef, nf, ei);
    copy_wcat_kernel<<<16384 / 256, 256>>>(w_e, w_n);
    // 4) h = acat @ wcat   (K=256, W in scratch)
    gemm128_kernel<<<Ee / 32, 128>>>(OFF_ACAT, 256, nullptr, OFF_WCAT, nullptr, 0, OFF_H);
    // 5) q,k,v
    gemm128_kernel<<<Ee / 32, 128>>>(OFF_H, 128, w_q, 0, nullptr, 0, OFF_Q);
    gemm128_kernel<<<Ee / 32, 128>>>(OFF_H, 128, w_k, 0, nullptr, 0, OFF_K);
    gemm128_kernel<<<Ee / 32, 128>>>(OFF_H, 128, w_v, 0, nullptr, 0, OFF_V);
    // 6) adjacency lists + sparse attention
    build_adj_kernel<<<Ee / 8, 256>>>(ei);
    attention_kernel<<<(Ee * 4) / 128, 128>>>();
    // 7) output projection + classifier
    gemm128_kernel<<<Ee / 32, 128>>>(OFF_ATT, 128, w_o, 0, nullptr, 0, OFF_T1);
    gemm128_kernel<<<Ee / 32, 128>>>(OFF_T1, 128, w1, 0, b1, 1, OFF_T2);
    final_fc_kernel<<<(Ee * 16) / 256, 256>>>(w2, b2, out);
}

// round 7
// speedup vs baseline: 1.3201x; 1.3201x over previous
#include <cuda_runtime.h>
#include <math.h>

#define Nn     2048
#define Ee     4096
#define NODE_K 1024
#define EDGE_K 2048
#define CAP    128

typedef unsigned long long u64;

// ---------------- scratch (static device memory; no allocs) ----------------
__device__ float g_f[3678208];
__device__ int   g_i[534528];

// float offsets into g_f
#define OFF_NS    0            // [N]
#define OFF_ES    2048         // [E]
#define OFF_H     8192         // [E][128]
#define OFF_Q     532480
#define OFF_K     1056768
#define OFF_V     1581056
#define OFF_ATT   2105344
#define OFF_T1    2629632
#define OFF_T2    3153920
// int offsets into g_i
#define IOFF_NCNT   0          // [N]  rank counts (contiguous with ECNT for bulk zero)
#define IOFF_ECNT   2048       // [E]
#define IOFF_ADJCNT 6144       // [E]
#define IOFF_ADJ    10240      // [E][CAP]

// ---------------- f32x2 helpers ----------------
__device__ __forceinline__ u64 pack2(float x) {
    u64 r; unsigned u = __float_as_uint(x);
    asm("mov.b64 %0, {%1, %1};" : "=l"(r) : "r"(u));
    return r;
}
__device__ __forceinline__ void ffma2(u64& d, u64 a, u64 b) {
    asm("fma.rn.f32x2 %0, %1, %2, %0;" : "+l"(d) : "l"(a), "l"(b));
}
__device__ __forceinline__ float2 unpack2(u64 a) {
    unsigned lo, hi;
    asm("mov.b64 {%0, %1}, %2;" : "=r"(lo), "=r"(hi) : "l"(a));
    return make_float2(__uint_as_float(lo), __uint_as_float(hi));
}

__device__ __forceinline__ float gelu_tanh(float x) {
    const float k0 = 0.7978845608028654f;   // sqrt(2/pi)
    float x3 = x * x * x;
    return 0.5f * x * (1.0f + tanhf(k0 * (x + 0.044715f * x3)));
}

// ---------------- 1) router scores (one warp/row) + zero rank counters ----------------
__global__ void router_scores_kernel(const float* __restrict__ nf,
                                     const float* __restrict__ ef,
                                     const float* __restrict__ wrn,
                                     const float* __restrict__ wre)
{
    int gt = blockIdx.x * blockDim.x + threadIdx.x;
    if (gt < Nn + Ee) g_i[gt] = 0;          // zero NCNT+ECNT (contiguous)
    int w    = gt >> 5;
    int lane = threadIdx.x & 31;
    if (w >= Nn + Ee) return;
    const float* row; const float* wt; float* outp; int idx;
    if (w < Nn) { idx = w;      row = nf + (size_t)idx * 128; wt = wrn; outp = g_f + OFF_NS; }
    else        { idx = w - Nn; row = ef + (size_t)idx * 128; wt = wre; outp = g_f + OFF_ES; }
    float s = 0.f;
    #pragma unroll
    for (int i = lane; i < 128; i += 32) s += row[i] * wt[i];
    #pragma unroll
    for (int o = 16; o; o >>= 1) s += __shfl_xor_sync(0xffffffffu, s, o);
    if (lane == 0) outp[idx] = s;
}

// ---------------- 2) blocked rank counting for both top-k sets ----------------
// node: 8 i-blocks x 4 j-chunks (512 j each) = 32 blocks; edge: 16 x 8 = 128 blocks.
__global__ __launch_bounds__(256) void topk_count_kernel()
{
    __shared__ float sj[512];
    int b = blockIdx.x, tid = threadIdx.x;
    const float* sc; int* cnt; int ibase, jbase;
    if (b < 32) { sc = g_f + OFF_NS; cnt = g_i + IOFF_NCNT;
                  ibase = (b & 7) * 256;  jbase = (b >> 3) * 512; }
    else        { int b2 = b - 32; sc = g_f + OFF_ES; cnt = g_i + IOFF_ECNT;
                  ibase = (b2 & 15) * 256; jbase = (b2 >> 4) * 512; }
    sj[tid]       = sc[jbase + tid];
    sj[tid + 256] = sc[jbase + tid + 256];
    __syncthreads();
    int i = ibase + tid;
    float v = sc[i];
    int c = 0;
    #pragma unroll 8
    for (int jj = 0; jj < 512; jj++) {
        float u = sj[jj];
        c += (u > v) || (u == v && (jbase + jj) < i);   // top_k tie-break: value desc, index asc
    }
    atomicAdd(&cnt[i], c);
}

// ---------------- 3) h-GEMM: h = [ef*emask | nf[src]+nf[dst]] @ [w_e ; w_n]  (K=256) ----------------
__global__ __launch_bounds__(256) void gemm_h_kernel(
    const float* __restrict__ ef, const float* __restrict__ nf,
    const int* __restrict__ ei,
    const float* __restrict__ w_e, const float* __restrict__ w_n)
{
    __shared__ float As[32][33];     // [k][m]
    __shared__ float Ws[32][128];    // [k][n]
    __shared__ int   snS[32], dnS[32];
    __shared__ float emS[32];
    int tid = threadIdx.x;
    int ty = tid >> 4, tx = tid & 15;
    int row0 = blockIdx.x * 32;

    if (tid < 32) {
        int r = row0 + tid;
        int sn = ei[r], dn = ei[Ee + r];
        snS[tid] = sn; dnS[tid] = dn;
        emS[tid] = (g_i[IOFF_ECNT + r] < EDGE_K &&
                    g_i[IOFF_NCNT + sn] < NODE_K &&
                    g_i[IOFF_NCNT + dn] < NODE_K) ? 1.0f : 0.0f;
    }
    __syncthreads();

    u64 acc[2][4];
    #pragma unroll
    for (int i = 0; i < 2; i++)
        #pragma unroll
        for (int j = 0; j < 4; j++) acc[i][j] = 0ull;

    for (int k0 = 0; k0 < 256; k0 += 32) {
        // A tile on the fly
        #pragma unroll
        for (int i = tid; i < 1024; i += 256) {
            int r = i >> 5, c = i & 31;
            float val;
            if (k0 < 128) {
                val = ef[(size_t)(row0 + r) * 128 + k0 + c] * emS[r];
            } else {
                int cc = k0 - 128 + c;
                val = nf[(size_t)snS[r] * 128 + cc] + nf[(size_t)dnS[r] * 128 + cc];
            }
            As[c][r] = val;
        }
        // W tile (row select between w_e / w_n)
        #pragma unroll
        for (int i = tid; i < 1024; i += 256) {
            int r = i >> 5, c = i & 31;
            const float* Wrow = (k0 < 128) ? (w_e + (size_t)(k0 + r) * 128)
                                           : (w_n + (size_t)(k0 - 128 + r) * 128);
            ((float4*)&Ws[r][0])[c] = ((const float4*)Wrow)[c];
        }
        __syncthreads();
        #pragma unroll
        for (int kk = 0; kk < 32; kk++) {
            u64 a0 = pack2(As[kk][ty * 2 + 0]);
            u64 a1 = pack2(As[kk][ty * 2 + 1]);
            const u64* w8 = (const u64*)&Ws[kk][0];
            u64 w0 = w8[tx * 2], w1 = w8[tx * 2 + 1];
            u64 w2 = w8[32 + tx * 2], w3 = w8[32 + tx * 2 + 1];
            ffma2(acc[0][0], a0, w0); ffma2(acc[0][1], a0, w1);
            ffma2(acc[0][2], a0, w2); ffma2(acc[0][3], a0, w3);
            ffma2(acc[1][0], a1, w0); ffma2(acc[1][1], a1, w1);
            ffma2(acc[1][2], a1, w2); ffma2(acc[1][3], a1, w3);
        }
        __syncthreads();
    }

    float* C = g_f + OFF_H;
    #pragma unroll
    for (int i = 0; i < 2; i++) {
        int row = row0 + ty * 2 + i;
        float2 p0 = unpack2(acc[i][0]), p1 = unpack2(acc[i][1]);
        float2 p2 = unpack2(acc[i][2]), p3 = unpack2(acc[i][3]);
        ((float4*)(C + (size_t)row * 128))[tx]      = make_float4(p0.x, p0.y, p1.x, p1.y);
        ((float4*)(C + (size_t)row * 128))[16 + tx] = make_float4(p2.x, p2.y, p3.x, p3.y);
    }
}

// ---------------- 4) fused QKV GEMM: [Q|K|V] = H @ [w_q|w_k|w_v]  (N=384, k-tile 16) ----------------
__global__ __launch_bounds__(256) void gemm_qkv_kernel(
    const float* __restrict__ w_q, const float* __restrict__ w_k, const float* __restrict__ w_v)
{
    __shared__ float As[16][33];     // [k][m]
    __shared__ float Ws[16][384];    // [k][n]
    int tid = threadIdx.x;
    int ty = tid >> 5, tx = tid & 31;   // ty: 4 rows each; tx: 3 float4 col groups
    int row0 = blockIdx.x * 32;
    const float* A = g_f + OFF_H;

    u64 acc[4][6];
    #pragma unroll
    for (int i = 0; i < 4; i++)
        #pragma unroll
        for (int j = 0; j < 6; j++) acc[i][j] = 0ull;

    for (int k0 = 0; k0 < 128; k0 += 16) {
        #pragma unroll
        for (int i = tid; i < 512; i += 256) {
            int m = i >> 4, kk = i & 15;
            As[kk][m] = A[(size_t)(row0 + m) * 128 + k0 + kk];
        }
        #pragma unroll
        for (int i = tid; i < 1536; i += 256) {
            int r = i / 96, g = i % 96;
            int mat = g >> 5, c4 = g & 31;
            const float* Wp = ((mat == 0) ? w_q : (mat == 1) ? w_k : w_v) + (size_t)(k0 + r) * 128;
            ((float4*)&Ws[r][0])[g] = ((const float4*)Wp)[c4];
        }
        __syncthreads();
        #pragma unroll
        for (int kk = 0; kk < 16; kk++) {
            const u64* w8 = (const u64*)&Ws[kk][0];
            u64 wp[6];
            wp[0] = w8[tx * 2];       wp[1] = w8[tx * 2 + 1];
            wp[2] = w8[64 + tx * 2];  wp[3] = w8[64 + tx * 2 + 1];
            wp[4] = w8[128 + tx * 2]; wp[5] = w8[128 + tx * 2 + 1];
            #pragma unroll
            for (int i = 0; i < 4; i++) {
                u64 a2 = pack2(As[kk][ty * 4 + i]);
                #pragma unroll
                for (int j = 0; j < 6; j++) ffma2(acc[i][j], a2, wp[j]);
            }
        }
        __syncthreads();
    }

    float* Q = g_f + OFF_Q; float* K = g_f + OFF_K; float* V = g_f + OFF_V;
    #pragma unroll
    for (int i = 0; i < 4; i++) {
        int row = row0 + ty * 4 + i;
        float2 a0 = unpack2(acc[i][0]), a1 = unpack2(acc[i][1]);
        float2 b0 = unpack2(acc[i][2]), b1 = unpack2(acc[i][3]);
        float2 c0 = unpack2(acc[i][4]), c1 = unpack2(acc[i][5]);
        ((float4*)(Q + (size_t)row * 128))[tx] = make_float4(a0.x, a0.y, a1.x, a1.y);
        ((float4*)(K + (size_t)row * 128))[tx] = make_float4(b0.x, b0.y, b1.x, b1.y);
        ((float4*)(V + (size_t)row * 128))[tx] = make_float4(c0.x, c0.y, c1.x, c1.y);
    }
}

// ---------------- generic GEMM C[M,128] = act(A@W + bias), f32x2 inner ----------------
__global__ __launch_bounds__(256) void gemm128_kernel(
    int a_off, const float* __restrict__ W,
    const float* __restrict__ bias, int act, int c_off)
{
    __shared__ float As[32][33];
    __shared__ float Ws[32][128];
    int tid = threadIdx.x;
    int ty = tid >> 4, tx = tid & 15;
    int row0 = blockIdx.x * 32;
    const float* A = g_f + a_off;
    float* C = g_f + c_off;

    u64 acc[2][4];
    #pragma unroll
    for (int i = 0; i < 2; i++)
        #pragma unroll
        for (int j = 0; j < 4; j++) acc[i][j] = 0ull;

    for (int k0 = 0; k0 < 128; k0 += 32) {
        #pragma unroll
        for (int i = tid; i < 1024; i += 256) {
            int r = i >> 5, c = i & 31;
            As[c][r] = A[(size_t)(row0 + r) * 128 + k0 + c];
        }
        #pragma unroll
        for (int i = tid; i < 1024; i += 256) {
            int r = i >> 5, c = i & 31;
            ((float4*)&Ws[r][0])[c] = ((const float4*)(W + (size_t)(k0 + r) * 128))[c];
        }
        __syncthreads();
        #pragma unroll
        for (int kk = 0; kk < 32; kk++) {
            u64 a0 = pack2(As[kk][ty * 2 + 0]);
            u64 a1 = pack2(As[kk][ty * 2 + 1]);
            const u64* w8 = (const u64*)&Ws[kk][0];
            u64 w0 = w8[tx * 2], w1 = w8[tx * 2 + 1];
            u64 w2 = w8[32 + tx * 2], w3 = w8[32 + tx * 2 + 1];
            ffma2(acc[0][0], a0, w0); ffma2(acc[0][1], a0, w1);
            ffma2(acc[0][2], a0, w2); ffma2(acc[0][3], a0, w3);
            ffma2(acc[1][0], a1, w0); ffma2(acc[1][1], a1, w1);
            ffma2(acc[1][2], a1, w2); ffma2(acc[1][3], a1, w3);
        }
        __syncthreads();
    }

    #pragma unroll
    for (int i = 0; i < 2; i++) {
        int row = row0 + ty * 2 + i;
        float o[8];
        float2 p0 = unpack2(acc[i][0]), p1 = unpack2(acc[i][1]);
        float2 p2 = unpack2(acc[i][2]), p3 = unpack2(acc[i][3]);
        o[0] = p0.x; o[1] = p0.y; o[2] = p1.x; o[3] = p1.y;
        o[4] = p2.x; o[5] = p2.y; o[6] = p3.x; o[7] = p3.y;
        #pragma unroll
        for (int g = 0; g < 2; g++) {
            #pragma unroll
            for (int j = 0; j < 4; j++) {
                int c = g * 64 + tx * 4 + j;
                float v = o[g * 4 + j];
                if (bias) v += bias[c];
                if (act == 1) v = gelu_tanh(v);
                o[g * 4 + j] = v;
            }
        }
        ((float4*)(C + (size_t)row * 128))[tx]      = make_float4(o[0], o[1], o[2], o[3]);
        ((float4*)(C + (size_t)row * 128))[16 + tx] = make_float4(o[4], o[5], o[6], o[7]);
    }
}

// ---------------- 5) adjacency lists: warp/query-edge, ei staged in shared ----------------
__global__ __launch_bounds__(256) void build_adj_kernel(const int* __restrict__ ei)
{
    __shared__ int ss[Ee];
    __shared__ int sd[Ee];
    for (int i = threadIdx.x; i < Ee; i += 256) { ss[i] = ei[i]; sd[i] = ei[Ee + i]; }
    __syncthreads();
    int e    = blockIdx.x * 8 + (threadIdx.x >> 5);
    int lane = threadIdx.x & 31;
    int qs = ss[e], qd = sd[e];
    int* adj = g_i + IOFF_ADJ + (size_t)e * CAP;
    int cnt = 0;
    for (int j0 = 0; j0 < Ee; j0 += 32) {
        int f  = j0 + lane;
        int fs = ss[f], fd = sd[f];
        bool a = (qs == fs) | (qs == fd) | (qd == fs) | (qd == fd);
        unsigned b = __ballot_sync(0xffffffffu, a);
        if (a) {
            int pos = cnt + __popc(b & ((1u << lane) - 1u));
            if (pos < CAP) adj[pos] = f;
        }
        cnt += __popc(b);
    }
    if (lane == 0) g_i[IOFF_ADJCNT + e] = (cnt < CAP) ? cnt : CAP;
}

// ---------------- 6) sparse attention: one thread per (edge, head), online softmax ----------------
__global__ __launch_bounds__(128) void attention_kernel()
{
    int t = blockIdx.x * blockDim.x + threadIdx.x;   // E*H threads
    int e = t >> 2;
    int h = t & 3;

    const float* q = g_f + OFF_Q;
    const float* k = g_f + OFF_K;
    const float* v = g_f + OFF_V;

    float qr[32];
    const float4* qp = (const float4*)(q + (size_t)e * 128 + h * 32);
    #pragma unroll
    for (int d = 0; d < 8; d++) {
        float4 qq = qp[d];
        qr[d * 4 + 0] = qq.x; qr[d * 4 + 1] = qq.y; qr[d * 4 + 2] = qq.z; qr[d * 4 + 3] = qq.w;
    }

    float m = -INFINITY, l = 0.f;
    float o[32];
    #pragma unroll
    for (int d = 0; d < 32; d++) o[d] = 0.f;

    const float scale = 0.17677669529663687f;   // 1/sqrt(32)
    int cnt = g_i[IOFF_ADJCNT + e];
    const int* myadj = g_i + IOFF_ADJ + (size_t)e * CAP;

    for (int i = 0; i < cnt; i++) {
        int f = myadj[i];
        const float4* kp = (const float4*)(k + (size_t)f * 128 + h * 32);
        float s = 0.f;
        #pragma unroll
        for (int d = 0; d < 8; d++) {
            float4 kk = kp[d];
            s += qr[d * 4 + 0] * kk.x + qr[d * 4 + 1] * kk.y
               + qr[d * 4 + 2] * kk.z + qr[d * 4 + 3] * kk.w;
        }
        s *= scale;
        if (s > m) {
            float c = expf(m - s);
            l *= c;
            #pragma unroll
            for (int d = 0; d < 32; d++) o[d] *= c;
            m = s;
        }
        float p = expf(s - m);
        l += p;
        const float4* vp = (const float4*)(v + (size_t)f * 128 + h * 32);
        #pragma unroll
        for (int d = 0; d < 8; d++) {
            float4 vv = vp[d];
            o[d * 4 + 0] += p * vv.x; o[d * 4 + 1] += p * vv.y;
            o[d * 4 + 2] += p * vv.z; o[d * 4 + 3] += p * vv.w;
        }
    }

    float inv = 1.0f / l;
    float* op = g_f + OFF_ATT + (size_t)e * 128 + h * 32;
    #pragma unroll
    for (int d = 0; d < 32; d++) op[d] = o[d] * inv;
}

// ---------------- 7) final classifier layer: logits[E,16] ----------------
__global__ void final_fc_kernel(const float* __restrict__ w2,
                                const float* __restrict__ b2,
                                float* __restrict__ out)
{
    int t = blockIdx.x * blockDim.x + threadIdx.x;   // E*16 threads
    int e = t >> 4, c = t & 15;
    float acc = b2[c];
    const float* xr = g_f + OFF_T2 + (size_t)e * 128;
    #pragma unroll 4
    for (int kk = 0; kk < 128; kk++) acc += xr[kk] * w2[kk * 16 + c];
    out[t] = acc;
}

// ---------------- launcher: 9 pure kernel launches, graph-capture-safe ----------------
extern "C" void kernel_launch(void* const* d_in, const int* in_sizes, int n_in,
                              void* d_out, int out_size)
{
    (void)in_sizes; (void)n_in; (void)out_size;
    const float* nf   = (const float*)d_in[0];
    const float* ef   = (const float*)d_in[1];
    const int*   ei   = (const int*)  d_in[2];
    const float* wrn  = (const float*)d_in[3];
    const float* wre  = (const float*)d_in[4];
    const float* w_e  = (const float*)d_in[5];
    const float* w_n  = (const float*)d_in[6];
    const float* w_q  = (const float*)d_in[7];
    const float* w_k  = (const float*)d_in[8];
    const float* w_v  = (const float*)d_in[9];
    const float* w_o  = (const float*)d_in[10];
    const float* w1   = (const float*)d_in[11];
    const float* b1   = (const float*)d_in[12];
    const float* w2   = (const float*)d_in[13];
    const float* b2   = (const float*)d_in[14];
    float* out = (float*)d_out;

    router_scores_kernel<<<(Nn + Ee) * 32 / 256, 256>>>(nf, ef, wrn, wre);
    topk_count_kernel<<<160, 256>>>();
    gemm_h_kernel<<<Ee / 32, 256>>>(ef, nf, ei, w_e, w_n);
    gemm_qkv_kernel<<<Ee / 32, 256>>>(w_q, w_k, w_v);
    build_adj_kernel<<<Ee / 8, 256>>>(ei);
    attention_kernel<<<(Ee * 4) / 128, 128>>>();
    gemm128_kernel<<<Ee / 32, 256>>>(OFF_ATT, w_o, nullptr, 0, OFF_T1);
    gemm128_kernel<<<Ee / 32, 256>>>(OFF_T1, w1, b1, 1, OFF_T2);
    final_fc_kernel<<<(Ee * 16) / 256, 256>>>(w2, b2, out);
}

// round 8
// speedup vs baseline: 1.3651x; 1.0341x over previous
#include <cuda_runtime.h>
#include <math.h>

#define Nn     2048
#define Ee     4096
#define NODE_K 1024
#define EDGE_K 2048
#define CAP    128

typedef unsigned long long u64;

// ---------------- scratch (static device memory; no allocs) ----------------
__device__ float g_f[3678208];
__device__ int   g_i[534528];

// float offsets into g_f
#define OFF_NS    0            // [N]
#define OFF_ES    2048         // [E]
#define OFF_H     8192         // [E][128]
#define OFF_Q     532480
#define OFF_K     1056768
#define OFF_V     1581056
#define OFF_ATT   2105344
#define OFF_T1    2629632
#define OFF_T2    3153920
// int offsets into g_i
#define IOFF_NCNT   0          // [N]
#define IOFF_ECNT   2048       // [E]
#define IOFF_ADJCNT 6144       // [E]
#define IOFF_ADJ    10240      // [E][CAP]

// ---------------- f32x2 helpers ----------------
__device__ __forceinline__ u64 pack2(float x) {
    u64 r; unsigned u = __float_as_uint(x);
    asm("mov.b64 %0, {%1, %1};" : "=l"(r) : "r"(u));
    return r;
}
__device__ __forceinline__ void ffma2(u64& d, u64 a, u64 b) {
    asm("fma.rn.f32x2 %0, %1, %2, %0;" : "+l"(d) : "l"(a), "l"(b));
}
__device__ __forceinline__ float2 unpack2(u64 a) {
    unsigned lo, hi;
    asm("mov.b64 {%0, %1}, %2;" : "=r"(lo), "=r"(hi) : "l"(a));
    return make_float2(__uint_as_float(lo), __uint_as_float(hi));
}

__device__ __forceinline__ float gelu_tanh(float x) {
    const float k0 = 0.7978845608028654f;   // sqrt(2/pi)
    float x3 = x * x * x;
    return 0.5f * x * (1.0f + tanhf(k0 * (x + 0.044715f * x3)));
}

// ---------------- 1) router scores (one warp/row) + zero rank counters ----------------
__global__ void router_scores_kernel(const float* __restrict__ nf,
                                     const float* __restrict__ ef,
                                     const float* __restrict__ wrn,
                                     const float* __restrict__ wre)
{
    int gt = blockIdx.x * blockDim.x + threadIdx.x;
    if (gt < Nn + Ee) g_i[gt] = 0;          // zero NCNT+ECNT (contiguous)
    int w    = gt >> 5;
    int lane = threadIdx.x & 31;
    if (w >= Nn + Ee) return;
    const float* row; const float* wt; float* outp; int idx;
    if (w < Nn) { idx = w;      row = nf + (size_t)idx * 128; wt = wrn; outp = g_f + OFF_NS; }
    else        { idx = w - Nn; row = ef + (size_t)idx * 128; wt = wre; outp = g_f + OFF_ES; }
    float s = 0.f;
    #pragma unroll
    for (int i = lane; i < 128; i += 32) s += row[i] * wt[i];
    #pragma unroll
    for (int o = 16; o; o >>= 1) s += __shfl_xor_sync(0xffffffffu, s, o);
    if (lane == 0) outp[idx] = s;
}

// ---------------- 2) blocked rank counting for both top-k sets ----------------
__global__ __launch_bounds__(256) void topk_count_kernel()
{
    __shared__ float sj[512];
    int b = blockIdx.x, tid = threadIdx.x;
    const float* sc; int* cnt; int ibase, jbase;
    if (b < 32) { sc = g_f + OFF_NS; cnt = g_i + IOFF_NCNT;
                  ibase = (b & 7) * 256;  jbase = (b >> 3) * 512; }
    else        { int b2 = b - 32; sc = g_f + OFF_ES; cnt = g_i + IOFF_ECNT;
                  ibase = (b2 & 15) * 256; jbase = (b2 >> 4) * 512; }
    sj[tid]       = sc[jbase + tid];
    sj[tid + 256] = sc[jbase + tid + 256];
    __syncthreads();
    int i = ibase + tid;
    float v = sc[i];
    int c = 0;
    #pragma unroll 8
    for (int jj = 0; jj < 512; jj++) {
        float u = sj[jj];
        c += (u > v) || (u == v && (jbase + jj) < i);
    }
    atomicAdd(&cnt[i], c);
}

// ---------------- 3) h-GEMM: h = [ef*emask | nf[src]+nf[dst]] @ [w_e ; w_n]  (K=256) ----------------
// BM=32, 256 threads, thread tile 2Mx8N, reg-prefetch pipeline, duplicated-A smem.
__global__ __launch_bounds__(256) void gemm_h_kernel(
    const float* __restrict__ ef, const float* __restrict__ nf,
    const int* __restrict__ ei,
    const float* __restrict__ w_e, const float* __restrict__ w_n)
{
    __shared__ u64 As2[32][33];                       // [k][m] duplicated pairs
    __shared__ __align__(16) float Ws[32][128];       // [k][n]
    __shared__ int   snS[32], dnS[32];
    __shared__ float emS[32];
    int tid = threadIdx.x;
    int ty = tid >> 4, tx = tid & 15;
    int row0 = blockIdx.x * 32;

    if (tid < 32) {
        int r = row0 + tid;
        int sn = ei[r], dn = ei[Ee + r];
        snS[tid] = sn; dnS[tid] = dn;
        emS[tid] = (g_i[IOFF_ECNT + r] < EDGE_K &&
                    g_i[IOFF_NCNT + sn] < NODE_K &&
                    g_i[IOFF_NCNT + dn] < NODE_K) ? 1.0f : 0.0f;
    }
    __syncthreads();

    u64 acc[2][4];
    #pragma unroll
    for (int i = 0; i < 2; i++)
        #pragma unroll
        for (int j = 0; j < 4; j++) acc[i][j] = 0ull;

    float  a_pf[4];
    float4 w_pf[4];

    // prefetch tile 0
    #pragma unroll
    for (int s = 0; s < 4; s++) {
        int i = tid + s * 256;
        int r = i >> 5, c = i & 31;
        a_pf[s] = ef[(size_t)(row0 + r) * 128 + c] * emS[r];
        w_pf[s] = ((const float4*)(w_e + (size_t)r * 128))[c];
    }

    for (int t = 0; t < 8; t++) {
        // STS staged regs
        #pragma unroll
        for (int s = 0; s < 4; s++) {
            int i = tid + s * 256;
            int r = i >> 5, c = i & 31;
            As2[c][r] = pack2(a_pf[s]);
            ((float4*)&Ws[r][0])[c] = w_pf[s];
        }
        __syncthreads();
        // prefetch next tile (overlaps compute)
        if (t + 1 < 8) {
            int k0 = (t + 1) * 32;
            #pragma unroll
            for (int s = 0; s < 4; s++) {
                int i = tid + s * 256;
                int r = i >> 5, c = i & 31;
                if (k0 < 128) {
                    a_pf[s] = ef[(size_t)(row0 + r) * 128 + k0 + c] * emS[r];
                    w_pf[s] = ((const float4*)(w_e + (size_t)(k0 + r) * 128))[c];
                } else {
                    int cc = k0 - 128 + c;
                    a_pf[s] = nf[(size_t)snS[r] * 128 + cc] + nf[(size_t)dnS[r] * 128 + cc];
                    w_pf[s] = ((const float4*)(w_n + (size_t)(k0 - 128 + r) * 128))[c];
                }
            }
        }
        #pragma unroll
        for (int kk = 0; kk < 32; kk++) {
            u64 a0 = As2[kk][ty * 2 + 0];
            u64 a1 = As2[kk][ty * 2 + 1];
            const u64* w8 = (const u64*)&Ws[kk][0];
            u64 w0 = w8[tx * 2], w1 = w8[tx * 2 + 1];
            u64 w2 = w8[32 + tx * 2], w3 = w8[32 + tx * 2 + 1];
            ffma2(acc[0][0], a0, w0); ffma2(acc[0][1], a0, w1);
            ffma2(acc[0][2], a0, w2); ffma2(acc[0][3], a0, w3);
            ffma2(acc[1][0], a1, w0); ffma2(acc[1][1], a1, w1);
            ffma2(acc[1][2], a1, w2); ffma2(acc[1][3], a1, w3);
        }
        __syncthreads();
    }

    float* C = g_f + OFF_H;
    #pragma unroll
    for (int i = 0; i < 2; i++) {
        int row = row0 + ty * 2 + i;
        float2 p0 = unpack2(acc[i][0]), p1 = unpack2(acc[i][1]);
        float2 p2 = unpack2(acc[i][2]), p3 = unpack2(acc[i][3]);
        ((float4*)(C + (size_t)row * 128))[tx]      = make_float4(p0.x, p0.y, p1.x, p1.y);
        ((float4*)(C + (size_t)row * 128))[16 + tx] = make_float4(p2.x, p2.y, p3.x, p3.y);
    }
}

// ---------------- generic K=128 GEMM, multi-matrix via blockIdx.y ----------------
// grid = (M/32, nmat). C[mat] = act(A @ W[mat] + bias)
__global__ __launch_bounds__(256) void gemm_kernel(
    int a_off,
    const float* __restrict__ W0, const float* __restrict__ W1, const float* __restrict__ W2,
    int c0, int c1, int c2,
    const float* __restrict__ bias, int act)
{
    int mat = blockIdx.y;
    const float* W = (mat == 0) ? W0 : (mat == 1) ? W1 : W2;
    int c_off      = (mat == 0) ? c0 : (mat == 1) ? c1 : c2;

    __shared__ u64 As2[32][33];
    __shared__ __align__(16) float Ws[32][128];
    int tid = threadIdx.x;
    int ty = tid >> 4, tx = tid & 15;
    int row0 = blockIdx.x * 32;
    const float* A = g_f + a_off;

    u64 acc[2][4];
    #pragma unroll
    for (int i = 0; i < 2; i++)
        #pragma unroll
        for (int j = 0; j < 4; j++) acc[i][j] = 0ull;

    float  a_pf[4];
    float4 w_pf[4];
    #pragma unroll
    for (int s = 0; s < 4; s++) {
        int i = tid + s * 256;
        int r = i >> 5, c = i & 31;
        a_pf[s] = A[(size_t)(row0 + r) * 128 + c];
        w_pf[s] = ((const float4*)(W + (size_t)r * 128))[c];
    }

    for (int t = 0; t < 4; t++) {
        #pragma unroll
        for (int s = 0; s < 4; s++) {
            int i = tid + s * 256;
            int r = i >> 5, c = i & 31;
            As2[c][r] = pack2(a_pf[s]);
            ((float4*)&Ws[r][0])[c] = w_pf[s];
        }
        __syncthreads();
        if (t + 1 < 4) {
            int k0 = (t + 1) * 32;
            #pragma unroll
            for (int s = 0; s < 4; s++) {
                int i = tid + s * 256;
                int r = i >> 5, c = i & 31;
                a_pf[s] = A[(size_t)(row0 + r) * 128 + k0 + c];
                w_pf[s] = ((const float4*)(W + (size_t)(k0 + r) * 128))[c];
            }
        }
        #pragma unroll
        for (int kk = 0; kk < 32; kk++) {
            u64 a0 = As2[kk][ty * 2 + 0];
            u64 a1 = As2[kk][ty * 2 + 1];
            const u64* w8 = (const u64*)&Ws[kk][0];
            u64 w0 = w8[tx * 2], w1 = w8[tx * 2 + 1];
            u64 w2 = w8[32 + tx * 2], w3 = w8[32 + tx * 2 + 1];
            ffma2(acc[0][0], a0, w0); ffma2(acc[0][1], a0, w1);
            ffma2(acc[0][2], a0, w2); ffma2(acc[0][3], a0, w3);
            ffma2(acc[1][0], a1, w0); ffma2(acc[1][1], a1, w1);
            ffma2(acc[1][2], a1, w2); ffma2(acc[1][3], a1, w3);
        }
        __syncthreads();
    }

    float* C = g_f + c_off;
    #pragma unroll
    for (int i = 0; i < 2; i++) {
        int row = row0 + ty * 2 + i;
        float o[8];
        float2 p0 = unpack2(acc[i][0]), p1 = unpack2(acc[i][1]);
        float2 p2 = unpack2(acc[i][2]), p3 = unpack2(acc[i][3]);
        o[0] = p0.x; o[1] = p0.y; o[2] = p1.x; o[3] = p1.y;
        o[4] = p2.x; o[5] = p2.y; o[6] = p3.x; o[7] = p3.y;
        #pragma unroll
        for (int g = 0; g < 2; g++) {
            #pragma unroll
            for (int j = 0; j < 4; j++) {
                int c = g * 64 + tx * 4 + j;
                float v = o[g * 4 + j];
                if (bias) v += bias[c];
                if (act == 1) v = gelu_tanh(v);
                o[g * 4 + j] = v;
            }
        }
        ((float4*)(C + (size_t)row * 128))[tx]      = make_float4(o[0], o[1], o[2], o[3]);
        ((float4*)(C + (size_t)row * 128))[16 + tx] = make_float4(o[4], o[5], o[6], o[7]);
    }
}

// ---------------- 5) adjacency lists: warp/query-edge, ei staged in shared ----------------
__global__ __launch_bounds__(256) void build_adj_kernel(const int* __restrict__ ei)
{
    __shared__ int ss[Ee];
    __shared__ int sd[Ee];
    for (int i = threadIdx.x; i < Ee; i += 256) { ss[i] = ei[i]; sd[i] = ei[Ee + i]; }
    __syncthreads();
    int e    = blockIdx.x * 8 + (threadIdx.x >> 5);
    int lane = threadIdx.x & 31;
    int qs = ss[e], qd = sd[e];
    int* adj = g_i + IOFF_ADJ + (size_t)e * CAP;
    int cnt = 0;
    for (int j0 = 0; j0 < Ee; j0 += 32) {
        int f  = j0 + lane;
        int fs = ss[f], fd = sd[f];
        bool a = (qs == fs) | (qs == fd) | (qd == fs) | (qd == fd);
        unsigned b = __ballot_sync(0xffffffffu, a);
        if (a) {
            int pos = cnt + __popc(b & ((1u << lane) - 1u));
            if (pos < CAP) adj[pos] = f;
        }
        cnt += __popc(b);
    }
    if (lane == 0) g_i[IOFF_ADJCNT + e] = (cnt < CAP) ? cnt : CAP;
}

// ---------------- 6) sparse attention: one thread per (edge, head), online softmax ----------------
__global__ __launch_bounds__(128) void attention_kernel()
{
    int t = blockIdx.x * blockDim.x + threadIdx.x;   // E*H threads
    int e = t >> 2;
    int h = t & 3;

    const float* q = g_f + OFF_Q;
    const float* k = g_f + OFF_K;
    const float* v = g_f + OFF_V;

    float qr[32];
    const float4* qp = (const float4*)(q + (size_t)e * 128 + h * 32);
    #pragma unroll
    for (int d = 0; d < 8; d++) {
        float4 qq = qp[d];
        qr[d * 4 + 0] = qq.x; qr[d * 4 + 1] = qq.y; qr[d * 4 + 2] = qq.z; qr[d * 4 + 3] = qq.w;
    }

    float m = -INFINITY, l = 0.f;
    float o[32];
    #pragma unroll
    for (int d = 0; d < 32; d++) o[d] = 0.f;

    const float scale = 0.17677669529663687f;
    int cnt = g_i[IOFF_ADJCNT + e];
    const int* myadj = g_i + IOFF_ADJ + (size_t)e * CAP;

    for (int i = 0; i < cnt; i++) {
        int f = myadj[i];
        const float4* kp = (const float4*)(k + (size_t)f * 128 + h * 32);
        float s = 0.f;
        #pragma unroll
        for (int d = 0; d < 8; d++) {
            float4 kk = kp[d];
            s += qr[d * 4 + 0] * kk.x + qr[d * 4 + 1] * kk.y
               + qr[d * 4 + 2] * kk.z + qr[d * 4 + 3] * kk.w;
        }
        s *= scale;
        if (s > m) {
            float c = expf(m - s);
            l *= c;
            #pragma unroll
            for (int d = 0; d < 32; d++) o[d] *= c;
            m = s;
        }
        float p = expf(s - m);
        l += p;
        const float4* vp = (const float4*)(v + (size_t)f * 128 + h * 32);
        #pragma unroll
        for (int d = 0; d < 8; d++) {
            float4 vv = vp[d];
            o[d * 4 + 0] += p * vv.x; o[d * 4 + 1] += p * vv.y;
            o[d * 4 + 2] += p * vv.z; o[d * 4 + 3] += p * vv.w;
        }
    }

    float inv = 1.0f / l;
    float* op = g_f + OFF_ATT + (size_t)e * 128 + h * 32;
    #pragma unroll
    for (int d = 0; d < 32; d++) op[d] = o[d] * inv;
}

// ---------------- 7) final classifier layer: logits[E,16] ----------------
__global__ void final_fc_kernel(const float* __restrict__ w2,
                                const float* __restrict__ b2,
                                float* __restrict__ out)
{
    int t = blockIdx.x * blockDim.x + threadIdx.x;   // E*16 threads
    int e = t >> 4, c = t & 15;
    float acc = b2[c];
    const float* xr = g_f + OFF_T2 + (size_t)e * 128;
    #pragma unroll 4
    for (int kk = 0; kk < 128; kk++) acc += xr[kk] * w2[kk * 16 + c];
    out[t] = acc;
}

// ---------------- launcher: 9 pure kernel launches, graph-capture-safe ----------------
extern "C" void kernel_launch(void* const* d_in, const int* in_sizes, int n_in,
                              void* d_out, int out_size)
{
    (void)in_sizes; (void)n_in; (void)out_size;
    const float* nf   = (const float*)d_in[0];
    const float* ef   = (const float*)d_in[1];
    const int*   ei   = (const int*)  d_in[2];
    const float* wrn  = (const float*)d_in[3];
    const float* wre  = (const float*)d_in[4];
    const float* w_e  = (const float*)d_in[5];
    const float* w_n  = (const float*)d_in[6];
    const float* w_q  = (const float*)d_in[7];
    const float* w_k  = (const float*)d_in[8];
    const float* w_v  = (const float*)d_in[9];
    const float* w_o  = (const float*)d_in[10];
    const float* w1   = (const float*)d_in[11];
    const float* b1   = (const float*)d_in[12];
    const float* w2   = (const float*)d_in[13];
    const float* b2   = (const float*)d_in[14];
    float* out = (float*)d_out;

    router_scores_kernel<<<(Nn + Ee) * 32 / 256, 256>>>(nf, ef, wrn, wre);
    topk_count_kernel<<<160, 256>>>();
    gemm_h_kernel<<<Ee / 32, 256>>>(ef, nf, ei, w_e, w_n);
    // fused QKV: 3 matrices via blockIdx.y -> 384 blocks
    gemm_kernel<<<dim3(Ee / 32, 3), 256>>>(OFF_H, w_q, w_k, w_v,
                                           OFF_Q, OFF_K, OFF_V, nullptr, 0);
    build_adj_kernel<<<Ee / 8, 256>>>(ei);
    attention_kernel<<<(Ee * 4) / 128, 128>>>();
    gemm_kernel<<<dim3(Ee / 32, 1), 256>>>(OFF_ATT, w_o, w_o, w_o,
                                           OFF_T1, OFF_T1, OFF_T1, nullptr, 0);
    gemm_kernel<<<dim3(Ee / 32, 1), 256>>>(OFF_T1, w1, w1, w1,
                                           OFF_T2, OFF_T2, OFF_T2, b1, 1);
    final_fc_kernel<<<(Ee * 16) / 256, 256>>>(w2, b2, out);
}